// round 14
// baseline (speedup 1.0000x reference)
#include <cuda_runtime.h>
#include <cuda_bf16.h>
#include <cstdint>

// B=32 images of 512x512 fp32 (output, density_map), 3 int64 bboxes/batch.
// R14: SM-balanced tiling. Grid 296 = exactly 2 CTAs on each of 148 SMs;
// 2048 tiles of 4096 floats/array, static stride assignment (98.9% balance
// vs 86.5% for batch-aligned grid 256). Tiles cross batches, so per-batch
// sums go through double atomicAdd accumulators (<=64 adds/address; double
// rounding noise << 1e-3 tol). Register double-buffer prefetch keeps MLP=8.
// 256-bit evict_last loads (R13) kept. Last-block finalize + replay reset.

#define IMG_H 512
#define IMG_W 512
#define HW (IMG_H * IMG_W)        // 262144 floats per image
#define NBATCH 32
#define NBOX 3
#define GRID 296
#define TILE_FLOATS 4096          // per array per tile (16KB)
#define NTILES 2048               // 32 batches x 64 tiles
#define TPB 64                    // tiles per batch

__device__ float  g_sq[GRID];
__device__ double g_bdv[NBATCH];
__device__ double g_boxv[NBOX * NBATCH];
__device__ unsigned int g_count;  // zero-init; reset by last block

// 256-bit streaming load with L2 evict_last hint (sm_103a).
struct F8 { float f[8]; };
__device__ __forceinline__ F8 ldg_el8(const float* p) {
    unsigned long long r0, r1, r2, r3;
    asm volatile("ld.global.nc.L2::evict_last.v4.b64 {%0,%1,%2,%3}, [%4];"
                 : "=l"(r0), "=l"(r1), "=l"(r2), "=l"(r3) : "l"(p));
    F8 v;
    v.f[0] = __uint_as_float((unsigned)r0); v.f[1] = __uint_as_float((unsigned)(r0 >> 32));
    v.f[2] = __uint_as_float((unsigned)r1); v.f[3] = __uint_as_float((unsigned)(r1 >> 32));
    v.f[4] = __uint_as_float((unsigned)r2); v.f[5] = __uint_as_float((unsigned)(r2 >> 32));
    v.f[6] = __uint_as_float((unsigned)r3); v.f[7] = __uint_as_float((unsigned)(r3 >> 32));
    return v;
}

__global__ __launch_bounds__(256, 2)
void crit_kernel(const float* __restrict__ out_p,
                 const float* __restrict__ dmp_p,
                 const long long* __restrict__ bbox_p,
                 float* __restrict__ out3,
                 const unsigned char* __restrict__ nobj_ptr)
{
    const int bid = blockIdx.x;
    const int t   = threadIdx.x;
    const int wid = t >> 5, lid = t & 31;

    // All 32 batches' clipped bboxes in shared (384 ints).
    __shared__ int sbb[NBATCH * NBOX * 4];
    for (int i = t; i < NBATCH * NBOX * 4; i += 256) {
        long long v = bbox_p[i];
        if (v < 0) v = 0;
        if (v > IMG_W) v = IMG_W;
        sbb[i] = (int)v;
    }
    __shared__ float wsum[8][5];
    __syncthreads();

    float blockSq = 0.f;            // meaningful in thread 0 only

    // ---- tile loop with register double-buffer prefetch ----
    int tau = bid;
    F8 oA[2], dA[2];
    {   // prime current tile
        const float* ob = out_p + (size_t)tau * TILE_FLOATS;
        const float* db = dmp_p + (size_t)tau * TILE_FLOATS;
        oA[0] = ldg_el8(ob + (size_t)t * 8);
        oA[1] = ldg_el8(ob + (size_t)(t + 256) * 8);
        dA[0] = ldg_el8(db + (size_t)t * 8);
        dA[1] = ldg_el8(db + (size_t)(t + 256) * 8);
    }

    while (true) {
        const int taun = tau + GRID;
        F8 oB[2], dB[2];
        if (taun < NTILES) {        // prefetch next tile
            const float* ob = out_p + (size_t)taun * TILE_FLOATS;
            const float* db = dmp_p + (size_t)taun * TILE_FLOATS;
            oB[0] = ldg_el8(ob + (size_t)t * 8);
            oB[1] = ldg_el8(ob + (size_t)(t + 256) * 8);
            dB[0] = ldg_el8(db + (size_t)t * 8);
            dB[1] = ldg_el8(db + (size_t)(t + 256) * 8);
        }

        // ---- compute current tile ----
        const int b = tau >> 6;                 // batch of this tile
        const int tbase = (tau & (TPB - 1)) * TILE_FLOATS;  // offset in image

        float sq = 0.f, bd = 0.f;
        float bs[NBOX] = {0.f, 0.f, 0.f};
#pragma unroll
        for (int c = 0; c < 2; c++) {
#pragma unroll
            for (int q = 0; q < 8; q++) {
                float dd = oA[c].f[q] - dA[c].f[q];
                sq += dd * dd;
                bd += dd;
            }
            int pix = tbase + (t + c * 256) * 8;
            int y   = pix >> 9;
            int x0  = pix & 511;                // 8-aligned, no row crossing
#pragma unroll
            for (int j = 0; j < NBOX; j++) {
                int y1 = sbb[(b * NBOX + j) * 4 + 1];
                int y2 = max(sbb[(b * NBOX + j) * 4 + 3], y1);
                if (y >= y1 && y < y2) {
                    int x1 = sbb[(b * NBOX + j) * 4 + 0];
                    int x2 = max(sbb[(b * NBOX + j) * 4 + 2], x1);
                    float s = 0.f;
#pragma unroll
                    for (int q = 0; q < 8; q++)
                        if (x0 + q >= x1 && x0 + q < x2) s += oA[c].f[q];
                    bs[j] += s;
                }
            }
        }

        // block reduce 5 floats
        float v5[5] = {sq, bd, bs[0], bs[1], bs[2]};
#pragma unroll
        for (int k = 0; k < 5; k++) {
#pragma unroll
            for (int off = 16; off > 0; off >>= 1)
                v5[k] += __shfl_xor_sync(0xFFFFFFFFu, v5[k], off);
        }
        if (lid == 0) {
#pragma unroll
            for (int k = 0; k < 5; k++) wsum[wid][k] = v5[k];
        }
        __syncthreads();
        if (t == 0) {
            float a[5] = {0, 0, 0, 0, 0};
#pragma unroll
            for (int w = 0; w < 8; w++) {
#pragma unroll
                for (int k = 0; k < 5; k++) a[k] += wsum[w][k];
            }
            blockSq += a[0];
            atomicAdd(&g_bdv[b], (double)a[1]);
#pragma unroll
            for (int j = 0; j < NBOX; j++)
                atomicAdd(&g_boxv[j * NBATCH + b], (double)a[2 + j]);
        }
        __syncthreads();            // wsum safe for next tile

        if (taun >= NTILES) break;
        tau = taun;
#pragma unroll
        for (int c = 0; c < 2; c++) { oA[c] = oB[c]; dA[c] = dB[c]; }
    }

    __shared__ bool isLast;
    if (t == 0) {
        g_sq[bid] = blockSq;
        __threadfence();
        unsigned int old = atomicAdd(&g_count, 1u);
        isLast = (old == GRID - 1);
    }
    __syncthreads();
    if (!isLast) return;

    // ---------- last-block finalization ----------
    __shared__ double shd[256];
    __shared__ double sh_out[4];    // [0]=count_sum, [1..3]=box margins

    {
        double s = (double)__ldcg(&g_sq[t]);
        if (t + 256 < GRID) s += (double)__ldcg(&g_sq[t + 256]);
        shd[t] = s;
    }
    __syncthreads();
#pragma unroll
    for (int o = 128; o > 0; o >>= 1) {
        if (t < o) shd[t] += shd[t + o];
        __syncthreads();
    }
    double total_sq = shd[0];

    if (wid == 0) {                 // count loss: lane = batch
        double v = g_bdv[lid];
        double c = v * v;
#pragma unroll
        for (int off = 16; off > 0; off >>= 1)
            c += __shfl_xor_sync(0xFFFFFFFFu, c, off);
        if (lid == 0) sh_out[0] = c;
    }
    if (wid >= 1 && wid <= 3) {     // box margins: lane = batch
        double r = 1.0 - g_boxv[(wid - 1) * NBATCH + lid];
        double m = (r > 0.0) ? r : 0.0;
#pragma unroll
        for (int off = 16; off > 0; off >>= 1)
            m += __shfl_xor_sync(0xFFFFFFFFu, m, off);
        if (lid == 0) sh_out[wid] = m;
    }
    __syncthreads();

    if (t == 0) {
        // Decode num_objects robustly (int32/int64 LE, or fp32).
        double num = 96.0;
        if (nobj_ptr) {
            int iv;
            memcpy(&iv, nobj_ptr, sizeof(int));
            if (iv > 0 && iv < (1 << 26)) {
                num = (double)iv;
            } else {
                float fv = __int_as_float(iv);
                if (fv > 0.5f && fv < 1e8f) num = (double)fv;
            }
        }
        out3[0] = (float)(total_sq / num);
        out3[1] = (float)(sh_out[0] / (double)NBATCH);
        out3[2] = (float)(sh_out[1] + sh_out[2] + sh_out[3]);
    }
    __syncthreads();
    // reset accumulators for next graph replay
    if (t < NBATCH) g_bdv[t] = 0.0;
    if (t < NBOX * NBATCH) g_boxv[t] = 0.0;
    if (t == 0) g_count = 0;
}

extern "C" void kernel_launch(void* const* d_in, const int* in_sizes, int n_in,
                              void* d_out, int out_size)
{
    const float*     out_p  = (const float*)d_in[0];
    const float*     dmp_p  = (const float*)d_in[1];
    const long long* bbox_p = (const long long*)d_in[2];
    const unsigned char* nobj = (n_in > 3) ? (const unsigned char*)d_in[3] : nullptr;
    (void)in_sizes; (void)out_size;

    crit_kernel<<<GRID, 256>>>(out_p, dmp_p, bbox_p, (float*)d_out, nobj);
}

// round 15
// speedup vs baseline: 1.0154x; 1.0154x over previous
#include <cuda_runtime.h>
#include <cuda_bf16.h>
#include <cstdint>

// B=32 images of 512x512 fp32 (output, density_map), 3 int64 bboxes/batch.
// R15: balanced AND contiguous. Block i owns contiguous tile range
// [i*2048/296,(i+1)*2048/296): ~7 adjacent 16KB tiles = ~112KB contiguous
// stream per array (R13's contiguity lever preserved), 98.9% SM balance
// (R14's goal, without its stride-296 contiguity bug). No syncthreads in
// the tile loop: sq is per-thread; batch-keyed bd/box sums flush via warp
// shuffle + per-warp double atomicAdd at batch boundaries (<=1 per block).
// 256-bit evict_last loads + adjacent-tile register double-buffer kept.

#define IMG_H 512
#define IMG_W 512
#define HW (IMG_H * IMG_W)        // 262144 floats per image
#define NBATCH 32
#define NBOX 3
#define GRID 296
#define TILE_FLOATS 4096          // per array per tile (16KB)
#define NTILES 2048               // 32 batches x 64 tiles
#define TPB 64                    // tiles per batch

__device__ float  g_sq[GRID];
__device__ double g_bdv[NBATCH];
__device__ double g_boxv[NBOX * NBATCH];
__device__ unsigned int g_count;  // zero-init; reset by last block

// 256-bit streaming load with L2 evict_last hint (sm_103a).
struct F8 { float f[8]; };
__device__ __forceinline__ F8 ldg_el8(const float* p) {
    unsigned long long r0, r1, r2, r3;
    asm volatile("ld.global.nc.L2::evict_last.v4.b64 {%0,%1,%2,%3}, [%4];"
                 : "=l"(r0), "=l"(r1), "=l"(r2), "=l"(r3) : "l"(p));
    F8 v;
    v.f[0] = __uint_as_float((unsigned)r0); v.f[1] = __uint_as_float((unsigned)(r0 >> 32));
    v.f[2] = __uint_as_float((unsigned)r1); v.f[3] = __uint_as_float((unsigned)(r1 >> 32));
    v.f[4] = __uint_as_float((unsigned)r2); v.f[5] = __uint_as_float((unsigned)(r2 >> 32));
    v.f[6] = __uint_as_float((unsigned)r3); v.f[7] = __uint_as_float((unsigned)(r3 >> 32));
    return v;
}

__global__ __launch_bounds__(256, 2)
void crit_kernel(const float* __restrict__ out_p,
                 const float* __restrict__ dmp_p,
                 const long long* __restrict__ bbox_p,
                 float* __restrict__ out3,
                 const unsigned char* __restrict__ nobj_ptr)
{
    const int bid = blockIdx.x;
    const int t   = threadIdx.x;
    const int wid = t >> 5, lid = t & 31;

    // Contiguous tile range for this block (98.9% balanced).
    const int ts = (bid * NTILES) / GRID;
    const int te = ((bid + 1) * NTILES) / GRID;

    // All 32 batches' clipped bboxes in shared (384 ints).
    __shared__ int sbb[NBATCH * NBOX * 4];
    for (int i = t; i < NBATCH * NBOX * 4; i += 256) {
        long long v = bbox_p[i];
        if (v < 0) v = 0;
        if (v > IMG_W) v = IMG_W;
        sbb[i] = (int)v;
    }
    __syncthreads();

    float sq = 0.f;                       // whole-range per-thread
    float bd = 0.f;                       // current-batch per-thread
    float bs[NBOX] = {0.f, 0.f, 0.f};     // current-batch per-thread

    // ---- tile loop: contiguous, double-buffered, sync-free ----
    F8 oA[2], dA[2];
    {
        const float* ob = out_p + (size_t)ts * TILE_FLOATS;
        const float* db = dmp_p + (size_t)ts * TILE_FLOATS;
        oA[0] = ldg_el8(ob + (size_t)t * 8);
        oA[1] = ldg_el8(ob + (size_t)(t + 256) * 8);
        dA[0] = ldg_el8(db + (size_t)t * 8);
        dA[1] = ldg_el8(db + (size_t)(t + 256) * 8);
    }

    for (int tau = ts; tau < te; tau++) {
        F8 oB[2], dB[2];
        if (tau + 1 < te) {               // prefetch adjacent tile
            const float* ob = out_p + (size_t)(tau + 1) * TILE_FLOATS;
            const float* db = dmp_p + (size_t)(tau + 1) * TILE_FLOATS;
            oB[0] = ldg_el8(ob + (size_t)t * 8);
            oB[1] = ldg_el8(ob + (size_t)(t + 256) * 8);
            dB[0] = ldg_el8(db + (size_t)t * 8);
            dB[1] = ldg_el8(db + (size_t)(t + 256) * 8);
        }

        const int b     = tau >> 6;
        const int tbase = (tau & (TPB - 1)) * TILE_FLOATS;

#pragma unroll
        for (int c = 0; c < 2; c++) {
#pragma unroll
            for (int q = 0; q < 8; q++) {
                float dd = oA[c].f[q] - dA[c].f[q];
                sq += dd * dd;
                bd += dd;
            }
            int pix = tbase + (t + c * 256) * 8;
            int y   = pix >> 9;
            int x0  = pix & 511;          // 8-aligned, no row crossing
#pragma unroll
            for (int j = 0; j < NBOX; j++) {
                int y1 = sbb[(b * NBOX + j) * 4 + 1];
                int y2 = max(sbb[(b * NBOX + j) * 4 + 3], y1);
                if (y >= y1 && y < y2) {
                    int x1 = sbb[(b * NBOX + j) * 4 + 0];
                    int x2 = max(sbb[(b * NBOX + j) * 4 + 2], x1);
                    float s = 0.f;
#pragma unroll
                    for (int q = 0; q < 8; q++)
                        if (x0 + q >= x1 && x0 + q < x2) s += oA[c].f[q];
                    bs[j] += s;
                }
            }
        }

        // Flush batch-keyed accumulators at batch boundary / range end.
        if (tau + 1 >= te || ((tau + 1) >> 6) != b) {
            float v4[4] = {bd, bs[0], bs[1], bs[2]};
#pragma unroll
            for (int k = 0; k < 4; k++) {
#pragma unroll
                for (int off = 16; off > 0; off >>= 1)
                    v4[k] += __shfl_xor_sync(0xFFFFFFFFu, v4[k], off);
            }
            if (lid == 0) {
                atomicAdd(&g_bdv[b], (double)v4[0]);
#pragma unroll
                for (int j = 0; j < NBOX; j++)
                    atomicAdd(&g_boxv[j * NBATCH + b], (double)v4[1 + j]);
            }
            bd = 0.f; bs[0] = 0.f; bs[1] = 0.f; bs[2] = 0.f;
        }

        if (tau + 1 < te) {
#pragma unroll
            for (int c = 0; c < 2; c++) { oA[c] = oB[c]; dA[c] = dB[c]; }
        }
    }

    // Block reduce sq, then arrive.
    {
#pragma unroll
        for (int off = 16; off > 0; off >>= 1)
            sq += __shfl_xor_sync(0xFFFFFFFFu, sq, off);
    }
    __shared__ float wsq[8];
    if (lid == 0) wsq[wid] = sq;
    __syncthreads();

    __shared__ bool isLast;
    if (t == 0) {
        float a = 0.f;
#pragma unroll
        for (int w = 0; w < 8; w++) a += wsq[w];
        g_sq[bid] = a;
        __threadfence();
        unsigned int old = atomicAdd(&g_count, 1u);
        isLast = (old == GRID - 1);
    }
    __syncthreads();
    if (!isLast) return;

    // ---------- last-block finalization ----------
    __shared__ double shd[256];
    __shared__ double sh_out[4];    // [0]=count_sum, [1..3]=box margins

    {
        double s = (double)__ldcg(&g_sq[t]);
        if (t + 256 < GRID) s += (double)__ldcg(&g_sq[t + 256]);
        shd[t] = s;
    }
    __syncthreads();
#pragma unroll
    for (int o = 128; o > 0; o >>= 1) {
        if (t < o) shd[t] += shd[t + o];
        __syncthreads();
    }
    double total_sq = shd[0];

    if (wid == 0) {                 // count loss: lane = batch
        double v = g_bdv[lid];
        double c = v * v;
#pragma unroll
        for (int off = 16; off > 0; off >>= 1)
            c += __shfl_xor_sync(0xFFFFFFFFu, c, off);
        if (lid == 0) sh_out[0] = c;
    }
    if (wid >= 1 && wid <= 3) {     // box margins: lane = batch
        double r = 1.0 - g_boxv[(wid - 1) * NBATCH + lid];
        double m = (r > 0.0) ? r : 0.0;
#pragma unroll
        for (int off = 16; off > 0; off >>= 1)
            m += __shfl_xor_sync(0xFFFFFFFFu, m, off);
        if (lid == 0) sh_out[wid] = m;
    }
    __syncthreads();

    if (t == 0) {
        // Decode num_objects robustly (int32/int64 LE, or fp32).
        double num = 96.0;
        if (nobj_ptr) {
            int iv;
            memcpy(&iv, nobj_ptr, sizeof(int));
            if (iv > 0 && iv < (1 << 26)) {
                num = (double)iv;
            } else {
                float fv = __int_as_float(iv);
                if (fv > 0.5f && fv < 1e8f) num = (double)fv;
            }
        }
        out3[0] = (float)(total_sq / num);
        out3[1] = (float)(sh_out[0] / (double)NBATCH);
        out3[2] = (float)(sh_out[1] + sh_out[2] + sh_out[3]);
    }
    __syncthreads();
    // reset accumulators for next graph replay
    if (t < NBATCH) g_bdv[t] = 0.0;
    if (t < NBOX * NBATCH) g_boxv[t] = 0.0;
    if (t == 0) g_count = 0;
}

extern "C" void kernel_launch(void* const* d_in, const int* in_sizes, int n_in,
                              void* d_out, int out_size)
{
    const float*     out_p  = (const float*)d_in[0];
    const float*     dmp_p  = (const float*)d_in[1];
    const long long* bbox_p = (const long long*)d_in[2];
    const unsigned char* nobj = (n_in > 3) ? (const unsigned char*)d_in[3] : nullptr;
    (void)in_sizes; (void)out_size;

    crit_kernel<<<GRID, 256>>>(out_p, dmp_p, bbox_p, (float*)d_out, nobj);
}

// round 16
// speedup vs baseline: 1.1231x; 1.1061x over previous
#include <cuda_runtime.h>
#include <cuda_bf16.h>
#include <cstdint>

// B=32 images of 512x512 fp32 (output, density_map), 3 int64 bboxes/batch.
// R16: R13 geometry (grid 256, batch-aligned 128KB contiguous spans,
// 256-bit evict_last loads, last-block fused finalize) with 128 threads
// per block at occ 2 -> 255-reg budget lets GRP=8 hold 16x32B = 512B per
// thread in flight (8x the latency-BW minimum) without register spill.
// R11's deepening attempt failed only on RF pressure at 256 thr; this is
// the same MLP depth with the registers to back it.

#define IMG_H 512
#define IMG_W 512
#define HW (IMG_H * IMG_W)        // 262144 floats per image
#define NBATCH 32
#define NBOX 3
#define BPB 8                     // blocks per batch
#define NB (NBATCH * BPB)         // 256 blocks
#define NTHREADS 128
#define CHUNKS 32                 // 8-float chunks per thread per array
#define GRP 8                     // chunk-batch depth (8 o + 8 d = 16 x 32B)
#define NGRP (CHUNKS / GRP)       // 4

__device__ float g_sq[NB];
__device__ float g_bd[NB];
__device__ float g_box[NBOX][NB];
__device__ unsigned int g_count;  // zero-init at load; reset by last block

// 256-bit streaming load with L2 evict_last hint (sm_103a).
struct F8 { float f[8]; };
__device__ __forceinline__ F8 ldg_el8(const float* p) {
    unsigned long long r0, r1, r2, r3;
    asm volatile("ld.global.nc.L2::evict_last.v4.b64 {%0,%1,%2,%3}, [%4];"
                 : "=l"(r0), "=l"(r1), "=l"(r2), "=l"(r3) : "l"(p));
    F8 v;
    v.f[0] = __uint_as_float((unsigned)r0); v.f[1] = __uint_as_float((unsigned)(r0 >> 32));
    v.f[2] = __uint_as_float((unsigned)r1); v.f[3] = __uint_as_float((unsigned)(r1 >> 32));
    v.f[4] = __uint_as_float((unsigned)r2); v.f[5] = __uint_as_float((unsigned)(r2 >> 32));
    v.f[6] = __uint_as_float((unsigned)r3); v.f[7] = __uint_as_float((unsigned)(r3 >> 32));
    return v;
}

__global__ __launch_bounds__(NTHREADS, 2)
void crit_kernel(const float* __restrict__ out_p,
                 const float* __restrict__ dmp_p,
                 const long long* __restrict__ bbox_p,
                 float* __restrict__ out3,
                 const unsigned char* __restrict__ nobj_ptr)
{
    const int bid = blockIdx.x;
    const int b   = bid >> 3;     // batch
    const int e   = bid & 7;      // eighth within batch
    const int t   = threadIdx.x;
    const int wid = t >> 5, lid = t & 31;

    // Load + clip this batch's 3 bboxes into shared
    __shared__ int sbb[NBOX * 4];
    if (t < NBOX * 4) {
        long long v = bbox_p[(size_t)b * NBOX * 4 + t];
        if (v < 0) v = 0;
        if (v > IMG_W) v = IMG_W;
        sbb[t] = (int)v;
    }
    __syncthreads();

    int bx1[NBOX], by1[NBOX], bx2[NBOX], by2[NBOX];
#pragma unroll
    for (int j = 0; j < NBOX; j++) {
        bx1[j] = sbb[j * 4 + 0];
        by1[j] = sbb[j * 4 + 1];
        bx2[j] = max(sbb[j * 4 + 2], bx1[j]);
        by2[j] = max(sbb[j * 4 + 3], by1[j]);
    }

    // This block's contiguous region: 8-float chunks [e*4096, (e+1)*4096)
    const float* __restrict__ ob = out_p + (size_t)b * HW;
    const float* __restrict__ db = dmp_p + (size_t)b * HW;
    const int base = e * (CHUNKS * NTHREADS) + t;   // chunk index

    float sq = 0.f, bd = 0.f;
    float bs[NBOX] = {0.f, 0.f, 0.f};

#pragma unroll
    for (int g = 0; g < NGRP; g++) {
        F8 o_[GRP], d_[GRP];
        // Front-batch 16 x 256-bit loads (512B in flight per thread).
#pragma unroll
        for (int u = 0; u < GRP; u++) {
            int c = base + (g * GRP + u) * NTHREADS;
            o_[u] = ldg_el8(ob + (size_t)c * 8);
            d_[u] = ldg_el8(db + (size_t)c * 8);
        }
#pragma unroll
        for (int u = 0; u < GRP; u++) {
#pragma unroll
            for (int q = 0; q < 8; q++) {
                float dd = o_[u].f[q] - d_[u].f[q];
                sq += dd * dd;
                bd += dd;
            }
            int c   = base + (g * GRP + u) * NTHREADS;
            int pix = c << 3;                 // element index within image
            int y   = pix >> 9;
            int x0  = pix & 511;              // 8-aligned, no row crossing
#pragma unroll
            for (int j = 0; j < NBOX; j++) {
                if (y >= by1[j] && y < by2[j]) {
                    float s = 0.f;
#pragma unroll
                    for (int q = 0; q < 8; q++) {
                        if (x0 + q >= bx1[j] && x0 + q < bx2[j]) s += o_[u].f[q];
                    }
                    bs[j] += s;
                }
            }
        }
    }

    // Block reduce 5 floats: warp shuffle, then across 4 warps via shared.
    float v5[5] = {sq, bd, bs[0], bs[1], bs[2]};
#pragma unroll
    for (int k = 0; k < 5; k++) {
#pragma unroll
        for (int off = 16; off > 0; off >>= 1)
            v5[k] += __shfl_xor_sync(0xFFFFFFFFu, v5[k], off);
    }
    __shared__ float wsum[4][5];
    if (lid == 0) {
#pragma unroll
        for (int k = 0; k < 5; k++) wsum[wid][k] = v5[k];
    }
    __syncthreads();

    __shared__ bool isLast;
    if (t == 0) {
        float a0 = 0, a1 = 0, a2 = 0, a3 = 0, a4 = 0;
#pragma unroll
        for (int w = 0; w < 4; w++) {
            a0 += wsum[w][0]; a1 += wsum[w][1]; a2 += wsum[w][2];
            a3 += wsum[w][3]; a4 += wsum[w][4];
        }
        g_sq[bid]     = a0;
        g_bd[bid]     = a1;
        g_box[0][bid] = a2;
        g_box[1][bid] = a3;
        g_box[2][bid] = a4;
        __threadfence();
        unsigned int old = atomicAdd(&g_count, 1u);
        isLast = (old == NB - 1);
    }
    __syncthreads();
    if (!isLast) return;

    // ---------- last-block finalization (256 partials, L2-hot) ----------
    __shared__ double shd[NTHREADS];
    __shared__ double sh_out[4];   // [0]=count_sum, [1..3]=box margins

    shd[t] = (double)__ldcg(&g_sq[t]) + (double)__ldcg(&g_sq[t + NTHREADS]);
    __syncthreads();
#pragma unroll
    for (int o = NTHREADS / 2; o > 0; o >>= 1) {
        if (t < o) shd[t] += shd[t + o];
        __syncthreads();
    }
    double total_sq = shd[0];

    // warp 0: count loss. lane = batch, sum its 8 bd partials (fixed order).
    if (wid == 0) {
        double v = 0.0;
#pragma unroll
        for (int k = 0; k < BPB; k++)
            v += (double)__ldcg(&g_bd[lid * BPB + k]);
        double c = v * v;
#pragma unroll
        for (int off = 16; off > 0; off >>= 1)
            c += __shfl_xor_sync(0xFFFFFFFFu, c, off);
        if (lid == 0) sh_out[0] = c;
    }
    // warps 1-3: box j margin sums. lane = batch.
    if (wid >= 1 && wid <= 3) {
        int j = wid - 1;
        double v = 0.0;
#pragma unroll
        for (int k = 0; k < BPB; k++)
            v += (double)__ldcg(&g_box[j][lid * BPB + k]);
        double r = 1.0 - v;
        double m = (r > 0.0) ? r : 0.0;
#pragma unroll
        for (int off = 16; off > 0; off >>= 1)
            m += __shfl_xor_sync(0xFFFFFFFFu, m, off);
        if (lid == 0) sh_out[wid] = m;
    }
    __syncthreads();

    if (t == 0) {
        // Decode num_objects robustly (int32/int64 LE, or fp32).
        double num = 96.0;
        if (nobj_ptr) {
            int iv;
            memcpy(&iv, nobj_ptr, sizeof(int));
            if (iv > 0 && iv < (1 << 26)) {
                num = (double)iv;
            } else {
                float fv = __int_as_float(iv);
                if (fv > 0.5f && fv < 1e8f) num = (double)fv;
            }
        }
        out3[0] = (float)(total_sq / num);
        out3[1] = (float)(sh_out[0] / (double)NBATCH);
        out3[2] = (float)(sh_out[1] + sh_out[2] + sh_out[3]);
        g_count = 0;   // reset for next graph replay
    }
}

extern "C" void kernel_launch(void* const* d_in, const int* in_sizes, int n_in,
                              void* d_out, int out_size)
{
    const float*     out_p  = (const float*)d_in[0];
    const float*     dmp_p  = (const float*)d_in[1];
    const long long* bbox_p = (const long long*)d_in[2];
    const unsigned char* nobj = (n_in > 3) ? (const unsigned char*)d_in[3] : nullptr;
    (void)in_sizes; (void)out_size;

    crit_kernel<<<NB, NTHREADS>>>(out_p, dmp_p, bbox_p, (float*)d_out, nobj);
}